// round 1
// baseline (speedup 1.0000x reference)
#include <cuda_runtime.h>
#include <stdint.h>

#define NN 100000
#define NE 1600000
#define IN_DIM 128
#define HID_DIM 256
#define OUT_DIM 64

// ---------------- device scratch (no allocations allowed) ----------------
__device__ __align__(16) float g_norm_src[NN];
__device__ __align__(16) float g_norm_dst[NN];
__device__ __align__(16) float g_xagg[(size_t)NN * IN_DIM];    // 51.2 MB
__device__ __align__(16) float g_hidden[(size_t)NN * HID_DIM]; // 102.4 MB
__device__ __align__(16) float g_ypre[(size_t)NN * OUT_DIM];   // 25.6 MB

// ---------------- zero init ----------------
__global__ void k_zero(float4* __restrict__ dout4, int n_nodes) {
    int i = blockIdx.x * blockDim.x + threadIdx.x;
    int stride = gridDim.x * blockDim.x;
    const float4 z = make_float4(0.f, 0.f, 0.f, 0.f);
    const int nx4 = n_nodes * (IN_DIM / 4);
    float4* xagg4 = reinterpret_cast<float4*>(g_xagg);
    for (int j = i; j < nx4; j += stride) xagg4[j] = z;
    const int no4 = n_nodes * (OUT_DIM / 4);
    for (int j = i; j < no4; j += stride) dout4[j] = z;
    for (int j = i; j < n_nodes; j += stride) { g_norm_src[j] = 0.f; g_norm_dst[j] = 0.f; }
}

// ---------------- degrees ----------------
__global__ void k_degree(const int* __restrict__ src, const int* __restrict__ dst, int n_edges) {
    int i = blockIdx.x * blockDim.x + threadIdx.x;
    int stride = gridDim.x * blockDim.x;
    for (int e = i; e < n_edges; e += stride) {
        atomicAdd(&g_norm_src[src[e]], 1.0f);
        atomicAdd(&g_norm_dst[dst[e]], 1.0f);
    }
}

__global__ void k_norm(int n_nodes) {
    int i = blockIdx.x * blockDim.x + threadIdx.x;
    if (i < n_nodes) {
        g_norm_src[i] = rsqrtf(fmaxf(g_norm_src[i], 1.0f));
        g_norm_dst[i] = rsqrtf(fmaxf(g_norm_dst[i], 1.0f));
    }
}

// ---------------- SpMM1: xagg[dst] += h[src] * norm_src[src] (128 floats/edge) ----------------
// warp per edge, 32 x float4
__global__ void k_spmm1(const float* __restrict__ h,
                        const int* __restrict__ src, const int* __restrict__ dst,
                        int n_edges) {
    int e = blockIdx.x * 8 + (threadIdx.x >> 5);
    if (e >= n_edges) return;
    int lane = threadIdx.x & 31;
    int s = src[e], d = dst[e];
    float ns = g_norm_src[s];
    const float4* hrow = reinterpret_cast<const float4*>(h + (size_t)s * IN_DIM);
    float4* orow = reinterpret_cast<float4*>(g_xagg + (size_t)d * IN_DIM);
    float4 v = hrow[lane];
    v.x *= ns; v.y *= ns; v.z *= ns; v.w *= ns;
    asm volatile("red.global.add.v4.f32 [%0], {%1,%2,%3,%4};"
                 :: "l"(orow + lane), "f"(v.x), "f"(v.y), "f"(v.z), "f"(v.w)
                 : "memory");
}

// ---------------- GEMM1: hidden = relu((xagg * norm_dst) @ W1 + b1) * clip(p,0,1) ----------------
// 64x64 tile, BK=16, 256 threads, 4x4 microtile
__global__ void k_gemm1(const float* __restrict__ W1, const float* __restrict__ b1,
                        const float* __restrict__ p, int n_nodes) {
    const int BM = 64, BN = 64, BK = 16;
    __shared__ float As[BK][BM];
    __shared__ float Bs[BK][BN];
    int m0 = blockIdx.x * BM;
    int n0 = blockIdx.y * BN;
    int tid = threadIdx.x;
    int ty = tid >> 4, tx = tid & 15;
    float acc[4][4] = {};
    for (int k0 = 0; k0 < IN_DIM; k0 += BK) {
        #pragma unroll
        for (int i = 0; i < 4; i++) {
            int idx = tid + i * 256;
            int r = idx >> 4, kk = idx & 15;
            int gr = m0 + r;
            float v = 0.f;
            if (gr < n_nodes) v = g_xagg[(size_t)gr * IN_DIM + k0 + kk] * g_norm_dst[gr];
            As[kk][r] = v;
        }
        #pragma unroll
        for (int i = 0; i < 4; i++) {
            int idx = tid + i * 256;
            int kk = idx >> 6, c = idx & 63;
            Bs[kk][c] = W1[(size_t)(k0 + kk) * HID_DIM + n0 + c];
        }
        __syncthreads();
        #pragma unroll
        for (int k = 0; k < BK; k++) {
            float a[4], bb[4];
            #pragma unroll
            for (int i = 0; i < 4; i++) a[i] = As[k][ty * 4 + i];
            #pragma unroll
            for (int j = 0; j < 4; j++) bb[j] = Bs[k][tx * 4 + j];
            #pragma unroll
            for (int i = 0; i < 4; i++)
                #pragma unroll
                for (int j = 0; j < 4; j++) acc[i][j] += a[i] * bb[j];
        }
        __syncthreads();
    }
    #pragma unroll
    for (int i = 0; i < 4; i++) {
        int gr = m0 + ty * 4 + i;
        if (gr >= n_nodes) continue;
        #pragma unroll
        for (int j = 0; j < 4; j++) {
            int gc = n0 + tx * 4 + j;
            float v = acc[i][j] + b1[gc];
            v = fmaxf(v, 0.f);
            float pc = fminf(fmaxf(p[gc], 0.f), 1.0f);
            g_hidden[(size_t)gr * HID_DIM + gc] = v * pc;
        }
    }
}

// ---------------- GEMM2: ypre = (hidden @ W2) * norm_src[row] ----------------
__global__ void k_gemm2(const float* __restrict__ W2, int n_nodes) {
    const int BM = 64, BN = 64, BK = 16;
    __shared__ float As[BK][BM];
    __shared__ float Bs[BK][BN];
    int m0 = blockIdx.x * BM;
    int tid = threadIdx.x;
    int ty = tid >> 4, tx = tid & 15;
    float acc[4][4] = {};
    for (int k0 = 0; k0 < HID_DIM; k0 += BK) {
        #pragma unroll
        for (int i = 0; i < 4; i++) {
            int idx = tid + i * 256;
            int r = idx >> 4, kk = idx & 15;
            int gr = m0 + r;
            float v = 0.f;
            if (gr < n_nodes) v = g_hidden[(size_t)gr * HID_DIM + k0 + kk];
            As[kk][r] = v;
        }
        #pragma unroll
        for (int i = 0; i < 4; i++) {
            int idx = tid + i * 256;
            int kk = idx >> 6, c = idx & 63;
            Bs[kk][c] = W2[(size_t)(k0 + kk) * OUT_DIM + c];
        }
        __syncthreads();
        #pragma unroll
        for (int k = 0; k < BK; k++) {
            float a[4], bb[4];
            #pragma unroll
            for (int i = 0; i < 4; i++) a[i] = As[k][ty * 4 + i];
            #pragma unroll
            for (int j = 0; j < 4; j++) bb[j] = Bs[k][tx * 4 + j];
            #pragma unroll
            for (int i = 0; i < 4; i++)
                #pragma unroll
                for (int j = 0; j < 4; j++) acc[i][j] += a[i] * bb[j];
        }
        __syncthreads();
    }
    #pragma unroll
    for (int i = 0; i < 4; i++) {
        int gr = m0 + ty * 4 + i;
        if (gr >= n_nodes) continue;
        float nsrc = g_norm_src[gr];
        #pragma unroll
        for (int j = 0; j < 4; j++) {
            int gc = tx * 4 + j;
            g_ypre[(size_t)gr * OUT_DIM + gc] = acc[i][j] * nsrc;
        }
    }
}

// ---------------- SpMM2: out[dst] += ypre[src] (64 floats/edge) ----------------
// 16 threads per edge, 16 edges per 256-thread block
__global__ void k_spmm2(const int* __restrict__ src, const int* __restrict__ dst,
                        float* __restrict__ out, int n_edges) {
    int e = blockIdx.x * 16 + (threadIdx.x >> 4);
    if (e >= n_edges) return;
    int lane = threadIdx.x & 15;
    int s = src[e], d = dst[e];
    const float4* yrow = reinterpret_cast<const float4*>(g_ypre + (size_t)s * OUT_DIM);
    float4* orow = reinterpret_cast<float4*>(out + (size_t)d * OUT_DIM);
    float4 v = yrow[lane];
    asm volatile("red.global.add.v4.f32 [%0], {%1,%2,%3,%4};"
                 :: "l"(orow + lane), "f"(v.x), "f"(v.y), "f"(v.z), "f"(v.w)
                 : "memory");
}

// ---------------- final: out = out * norm_dst[row] + b2[col] ----------------
__global__ void k_final(float* __restrict__ out, const float* __restrict__ b2, int n_nodes) {
    int i = blockIdx.x * blockDim.x + threadIdx.x;
    int total = n_nodes * (OUT_DIM / 4);
    if (i >= total) return;
    int row = i >> 4;          // 16 float4 per row
    int c4 = i & 15;
    float nd = g_norm_dst[row];
    float4 v = reinterpret_cast<float4*>(out)[i];
    const float4 bb = reinterpret_cast<const float4*>(b2)[c4];
    v.x = v.x * nd + bb.x;
    v.y = v.y * nd + bb.y;
    v.z = v.z * nd + bb.z;
    v.w = v.w * nd + bb.w;
    reinterpret_cast<float4*>(out)[i] = v;
}

// ---------------- launch ----------------
extern "C" void kernel_launch(void* const* d_in, const int* in_sizes, int n_in,
                              void* d_out, int out_size) {
    const float* h  = (const float*)d_in[0];
    const float* W1 = (const float*)d_in[1];
    const float* b1 = (const float*)d_in[2];
    const float* W2 = (const float*)d_in[3];
    const float* b2 = (const float*)d_in[4];
    const float* p  = (const float*)d_in[5];
    const int* src  = (const int*)d_in[6];
    const int* dst  = (const int*)d_in[7];

    const int n_nodes = in_sizes[0] / IN_DIM;   // 100000
    const int n_edges = in_sizes[6];            // 1600000
    float* out = (float*)d_out;

    // 1) zero accumulators + degree counters
    k_zero<<<4096, 256>>>(reinterpret_cast<float4*>(out), n_nodes);
    // 2) degrees
    k_degree<<<(n_edges + 255) / 256, 256>>>(src, dst, n_edges);
    // 3) norms
    k_norm<<<(n_nodes + 255) / 256, 256>>>(n_nodes);
    // 4) SpMM1 (warp per edge)
    k_spmm1<<<(n_edges + 7) / 8, 256>>>(h, src, dst, n_edges);
    // 5) GEMM1 + relu + bias + dropout scale
    {
        dim3 grid((n_nodes + 63) / 64, HID_DIM / 64);
        k_gemm1<<<grid, 256>>>(W1, b1, p, n_nodes);
    }
    // 6) GEMM2 + norm_src scale
    {
        dim3 grid((n_nodes + 63) / 64, 1);
        k_gemm2<<<grid, 256>>>(W2, n_nodes);
    }
    // 7) SpMM2
    k_spmm2<<<(n_edges + 15) / 16, 256>>>(src, dst, out, n_edges);
    // 8) final scale + bias
    k_final<<<(n_nodes * (OUT_DIM / 4) + 255) / 256, 256>>>(out, b2, n_nodes);
}

// round 2
// speedup vs baseline: 1.6791x; 1.6791x over previous
#include <cuda_runtime.h>
#include <cuda_bf16.h>
#include <stdint.h>

#define NN 100000
#define NN_PAD 100096           // 782 * 128
#define NE 1600000
#define IN_DIM 128
#define HID_DIM 256
#define OUT_DIM 64

// ---------------- device scratch ----------------
__device__ __align__(16) float g_norm_src[NN_PAD];
__device__ __align__(16) float g_norm_dst[NN_PAD];
__device__ __align__(16) float g_xagg[(size_t)NN_PAD * IN_DIM];
__device__ __align__(16) __nv_bfloat16 g_hid_hi[(size_t)NN_PAD * HID_DIM];
__device__ __align__(16) __nv_bfloat16 g_hid_lo[(size_t)NN_PAD * HID_DIM];
__device__ __align__(16) float g_ypre[(size_t)NN_PAD * OUT_DIM];

__device__ __forceinline__ void split_bf16(float v, __nv_bfloat16& hi, __nv_bfloat16& lo) {
    hi = __float2bfloat16(v);
    lo = __float2bfloat16(v - __bfloat162float(hi));
}

#define MMA_BF16(d, a, b0, b1)                                                  \
    asm volatile("mma.sync.aligned.m16n8k16.row.col.f32.bf16.bf16.f32 "         \
                 "{%0,%1,%2,%3}, {%4,%5,%6,%7}, {%8,%9}, {%0,%1,%2,%3};"        \
                 : "+f"(d[0]), "+f"(d[1]), "+f"(d[2]), "+f"(d[3])               \
                 : "r"(a[0]), "r"(a[1]), "r"(a[2]), "r"(a[3]), "r"(b0), "r"(b1))

// ---------------- zero init ----------------
__global__ void k_zero(float4* __restrict__ dout4, int n_nodes) {
    int i = blockIdx.x * blockDim.x + threadIdx.x;
    int stride = gridDim.x * blockDim.x;
    const float4 z = make_float4(0.f, 0.f, 0.f, 0.f);
    const int nx4 = NN_PAD * (IN_DIM / 4);
    float4* xagg4 = reinterpret_cast<float4*>(g_xagg);
    for (int j = i; j < nx4; j += stride) xagg4[j] = z;
    const int no4 = n_nodes * (OUT_DIM / 4);
    for (int j = i; j < no4; j += stride) dout4[j] = z;
    for (int j = i; j < NN_PAD; j += stride) { g_norm_src[j] = 0.f; g_norm_dst[j] = 0.f; }
    // pad rows of hid (never written by gemm1 epilogue) must stay zero
    const int hid_pad4 = (NN_PAD - NN) * (HID_DIM / 4);  // in bf16x4 = uint2 units
    uint2* hh = reinterpret_cast<uint2*>(g_hid_hi + (size_t)NN * HID_DIM);
    uint2* hl = reinterpret_cast<uint2*>(g_hid_lo + (size_t)NN * HID_DIM);
    const uint2 z2 = make_uint2(0u, 0u);
    for (int j = i; j < hid_pad4; j += stride) { hh[j] = z2; hl[j] = z2; }
}

// ---------------- degrees ----------------
__global__ void k_degree(const int* __restrict__ src, const int* __restrict__ dst, int n_edges) {
    int i = blockIdx.x * blockDim.x + threadIdx.x;
    int stride = gridDim.x * blockDim.x;
    for (int e = i; e < n_edges; e += stride) {
        atomicAdd(&g_norm_src[src[e]], 1.0f);
        atomicAdd(&g_norm_dst[dst[e]], 1.0f);
    }
}

__global__ void k_norm(int n_nodes) {
    int i = blockIdx.x * blockDim.x + threadIdx.x;
    if (i < n_nodes) {
        g_norm_src[i] = rsqrtf(fmaxf(g_norm_src[i], 1.0f));
        g_norm_dst[i] = rsqrtf(fmaxf(g_norm_dst[i], 1.0f));
    }
}

// ---------------- SpMM1: xagg[dst] += h[src]*norm_src[src], 4 edges/warp ----------------
__global__ void k_spmm1(const float* __restrict__ h,
                        const int* __restrict__ src, const int* __restrict__ dst,
                        int n_edges) {
    int w = (blockIdx.x * blockDim.x + threadIdx.x) >> 5;
    int lane = threadIdx.x & 31;
    int e0 = w * 4;
    if (e0 >= n_edges) return;
    int s[4], d[4];
    float ns[4];
    #pragma unroll
    for (int i = 0; i < 4; i++) {
        int e = min(e0 + i, n_edges - 1);
        s[i] = __ldg(&src[e]);
        d[i] = __ldg(&dst[e]);
    }
    #pragma unroll
    for (int i = 0; i < 4; i++) ns[i] = g_norm_src[s[i]];
    float4 v[4];
    #pragma unroll
    for (int i = 0; i < 4; i++)
        v[i] = reinterpret_cast<const float4*>(h + (size_t)s[i] * IN_DIM)[lane];
    #pragma unroll
    for (int i = 0; i < 4; i++) {
        if (e0 + i >= n_edges) break;
        float4 t = v[i];
        t.x *= ns[i]; t.y *= ns[i]; t.z *= ns[i]; t.w *= ns[i];
        float4* orow = reinterpret_cast<float4*>(g_xagg + (size_t)d[i] * IN_DIM);
        asm volatile("red.global.add.v4.f32 [%0], {%1,%2,%3,%4};"
                     :: "l"(orow + lane), "f"(t.x), "f"(t.y), "f"(t.z), "f"(t.w)
                     : "memory");
    }
}

// ---------------- GEMM common tile params ----------------
#define BM 128
#define BN 64
#define BK 32
#define KPAD 40   // bf16 elems per smem row (80B stride: 16B-aligned, conflict-free frags)

// GEMM1: hidden = relu((xagg*norm_dst) @ W1 + b1) * clip(p,0,1); store split bf16
__global__ __launch_bounds__(256) void k_gemm1(const float* __restrict__ W1,
                                               const float* __restrict__ b1,
                                               const float* __restrict__ p,
                                               int n_nodes) {
    __shared__ __align__(16) __nv_bfloat16 As_hi[BM * KPAD];
    __shared__ __align__(16) __nv_bfloat16 As_lo[BM * KPAD];
    __shared__ __align__(16) __nv_bfloat16 Bs_hi[BN * KPAD];
    __shared__ __align__(16) __nv_bfloat16 Bs_lo[BN * KPAD];

    const int m0 = blockIdx.x * BM;
    const int n0 = blockIdx.y * BN;
    const int tid = threadIdx.x;
    const int lane = tid & 31;
    const int wid = tid >> 5;
    const int warp_m = wid >> 2;   // 0..1  (64 rows)
    const int warp_n = wid & 3;    // 0..3  (16 cols)

    float acc[4][2][4];
    #pragma unroll
    for (int i = 0; i < 4; i++)
        #pragma unroll
        for (int j = 0; j < 2; j++)
            #pragma unroll
            for (int q = 0; q < 4; q++) acc[i][j][q] = 0.f;

    for (int k0 = 0; k0 < IN_DIM; k0 += BK) {
        // A tile: 128 rows x 32 k (fp32 -> split bf16). thread: 4 passes of one float4
        #pragma unroll
        for (int i = 0; i < 4; i++) {
            int row = (tid >> 3) + 32 * i;
            int kk = (tid & 7) * 4;
            int grow = m0 + row;
            float nd = g_norm_dst[grow];
            float4 v = *reinterpret_cast<const float4*>(&g_xagg[(size_t)grow * IN_DIM + k0 + kk]);
            v.x *= nd; v.y *= nd; v.z *= nd; v.w *= nd;
            __nv_bfloat16 h0, l0, h1, l1, h2, l2, h3, l3;
            split_bf16(v.x, h0, l0); split_bf16(v.y, h1, l1);
            split_bf16(v.z, h2, l2); split_bf16(v.w, h3, l3);
            *reinterpret_cast<__nv_bfloat162*>(&As_hi[row * KPAD + kk])     = __nv_bfloat162(h0, h1);
            *reinterpret_cast<__nv_bfloat162*>(&As_hi[row * KPAD + kk + 2]) = __nv_bfloat162(h2, h3);
            *reinterpret_cast<__nv_bfloat162*>(&As_lo[row * KPAD + kk])     = __nv_bfloat162(l0, l1);
            *reinterpret_cast<__nv_bfloat162*>(&As_lo[row * KPAD + kk + 2]) = __nv_bfloat162(l2, l3);
        }
        // B tile: 32 k x 64 n, transpose into [n][k]
        for (int i = tid; i < BK * BN; i += 256) {
            int k = i >> 6, n = i & 63;
            float v = W1[(size_t)(k0 + k) * HID_DIM + n0 + n];
            __nv_bfloat16 hi, lo;
            split_bf16(v, hi, lo);
            Bs_hi[n * KPAD + k] = hi;
            Bs_lo[n * KPAD + k] = lo;
        }
        __syncthreads();

        #pragma unroll
        for (int ks = 0; ks < 2; ks++) {
            const int kc = ks * 16 + 2 * (lane & 3);
            uint32_t ah[4][4], al[4][4];
            #pragma unroll
            for (int i = 0; i < 4; i++) {
                int r = warp_m * 64 + i * 16 + (lane >> 2);
                ah[i][0] = *reinterpret_cast<uint32_t*>(&As_hi[r * KPAD + kc]);
                ah[i][1] = *reinterpret_cast<uint32_t*>(&As_hi[(r + 8) * KPAD + kc]);
                ah[i][2] = *reinterpret_cast<uint32_t*>(&As_hi[r * KPAD + kc + 8]);
                ah[i][3] = *reinterpret_cast<uint32_t*>(&As_hi[(r + 8) * KPAD + kc + 8]);
                al[i][0] = *reinterpret_cast<uint32_t*>(&As_lo[r * KPAD + kc]);
                al[i][1] = *reinterpret_cast<uint32_t*>(&As_lo[(r + 8) * KPAD + kc]);
                al[i][2] = *reinterpret_cast<uint32_t*>(&As_lo[r * KPAD + kc + 8]);
                al[i][3] = *reinterpret_cast<uint32_t*>(&As_lo[(r + 8) * KPAD + kc + 8]);
            }
            #pragma unroll
            for (int j = 0; j < 2; j++) {
                int c = warp_n * 16 + j * 8 + (lane >> 2);
                uint32_t bh0 = *reinterpret_cast<uint32_t*>(&Bs_hi[c * KPAD + kc - 2 * (lane & 3) + 2 * (lane & 3)]);
                uint32_t bh1 = *reinterpret_cast<uint32_t*>(&Bs_hi[c * KPAD + kc + 8]);
                uint32_t bl0 = *reinterpret_cast<uint32_t*>(&Bs_lo[c * KPAD + kc]);
                uint32_t bl1 = *reinterpret_cast<uint32_t*>(&Bs_lo[c * KPAD + kc + 8]);
                #pragma unroll
                for (int i = 0; i < 4; i++) {
                    MMA_BF16(acc[i][j], ah[i], bh0, bh1);
                    MMA_BF16(acc[i][j], ah[i], bl0, bl1);
                    MMA_BF16(acc[i][j], al[i], bh0, bh1);
                }
            }
        }
        __syncthreads();
    }

    // epilogue: bias + relu + p-scale, split store
    #pragma unroll
    for (int i = 0; i < 4; i++) {
        int r = warp_m * 64 + i * 16 + (lane >> 2);
        #pragma unroll
        for (int j = 0; j < 2; j++) {
            int c0 = n0 + warp_n * 16 + j * 8 + 2 * (lane & 3);
            float bb0 = b1[c0], bb1 = b1[c0 + 1];
            float p0 = fminf(fmaxf(p[c0], 0.f), 1.f);
            float p1 = fminf(fmaxf(p[c0 + 1], 0.f), 1.f);
            #pragma unroll
            for (int hrow = 0; hrow < 2; hrow++) {
                int grow = m0 + r + 8 * hrow;
                if (grow >= n_nodes) continue;
                float v0 = fmaxf(acc[i][j][2 * hrow + 0] + bb0, 0.f) * p0;
                float v1 = fmaxf(acc[i][j][2 * hrow + 1] + bb1, 0.f) * p1;
                __nv_bfloat16 h0, l0, h1, l1;
                split_bf16(v0, h0, l0);
                split_bf16(v1, h1, l1);
                *reinterpret_cast<__nv_bfloat162*>(&g_hid_hi[(size_t)grow * HID_DIM + c0]) = __nv_bfloat162(h0, h1);
                *reinterpret_cast<__nv_bfloat162*>(&g_hid_lo[(size_t)grow * HID_DIM + c0]) = __nv_bfloat162(l0, l1);
            }
        }
    }
}

// GEMM2: ypre = (hidden @ W2) * norm_src[row]
__global__ __launch_bounds__(256) void k_gemm2(const float* __restrict__ W2, int n_nodes) {
    __shared__ __align__(16) __nv_bfloat16 As_hi[BM * KPAD];
    __shared__ __align__(16) __nv_bfloat16 As_lo[BM * KPAD];
    __shared__ __align__(16) __nv_bfloat16 Bs_hi[BN * KPAD];
    __shared__ __align__(16) __nv_bfloat16 Bs_lo[BN * KPAD];

    const int m0 = blockIdx.x * BM;
    const int tid = threadIdx.x;
    const int lane = tid & 31;
    const int wid = tid >> 5;
    const int warp_m = wid >> 2;
    const int warp_n = wid & 3;

    float acc[4][2][4];
    #pragma unroll
    for (int i = 0; i < 4; i++)
        #pragma unroll
        for (int j = 0; j < 2; j++)
            #pragma unroll
            for (int q = 0; q < 4; q++) acc[i][j][q] = 0.f;

    for (int k0 = 0; k0 < HID_DIM; k0 += BK) {
        // A tile: bf16 direct loads (hi & lo), 128 rows x 32 k: 512 uint4 per array
        #pragma unroll
        for (int i = 0; i < 2; i++) {
            int idx = tid + 256 * i;
            int row = idx >> 2;
            int q = idx & 3;
            uint4 vh = *reinterpret_cast<const uint4*>(&g_hid_hi[(size_t)(m0 + row) * HID_DIM + k0 + 8 * q]);
            uint4 vl = *reinterpret_cast<const uint4*>(&g_hid_lo[(size_t)(m0 + row) * HID_DIM + k0 + 8 * q]);
            *reinterpret_cast<uint4*>(&As_hi[row * KPAD + 8 * q]) = vh;
            *reinterpret_cast<uint4*>(&As_lo[row * KPAD + 8 * q]) = vl;
        }
        // B tile: W2[k0+k][n], transpose split
        for (int i = tid; i < BK * BN; i += 256) {
            int k = i >> 6, n = i & 63;
            float v = W2[(size_t)(k0 + k) * OUT_DIM + n];
            __nv_bfloat16 hi, lo;
            split_bf16(v, hi, lo);
            Bs_hi[n * KPAD + k] = hi;
            Bs_lo[n * KPAD + k] = lo;
        }
        __syncthreads();

        #pragma unroll
        for (int ks = 0; ks < 2; ks++) {
            const int kc = ks * 16 + 2 * (lane & 3);
            uint32_t ah[4][4], al[4][4];
            #pragma unroll
            for (int i = 0; i < 4; i++) {
                int r = warp_m * 64 + i * 16 + (lane >> 2);
                ah[i][0] = *reinterpret_cast<uint32_t*>(&As_hi[r * KPAD + kc]);
                ah[i][1] = *reinterpret_cast<uint32_t*>(&As_hi[(r + 8) * KPAD + kc]);
                ah[i][2] = *reinterpret_cast<uint32_t*>(&As_hi[r * KPAD + kc + 8]);
                ah[i][3] = *reinterpret_cast<uint32_t*>(&As_hi[(r + 8) * KPAD + kc + 8]);
                al[i][0] = *reinterpret_cast<uint32_t*>(&As_lo[r * KPAD + kc]);
                al[i][1] = *reinterpret_cast<uint32_t*>(&As_lo[(r + 8) * KPAD + kc]);
                al[i][2] = *reinterpret_cast<uint32_t*>(&As_lo[r * KPAD + kc + 8]);
                al[i][3] = *reinterpret_cast<uint32_t*>(&As_lo[(r + 8) * KPAD + kc + 8]);
            }
            #pragma unroll
            for (int j = 0; j < 2; j++) {
                int c = warp_n * 16 + j * 8 + (lane >> 2);
                uint32_t bh0 = *reinterpret_cast<uint32_t*>(&Bs_hi[c * KPAD + kc]);
                uint32_t bh1 = *reinterpret_cast<uint32_t*>(&Bs_hi[c * KPAD + kc + 8]);
                uint32_t bl0 = *reinterpret_cast<uint32_t*>(&Bs_lo[c * KPAD + kc]);
                uint32_t bl1 = *reinterpret_cast<uint32_t*>(&Bs_lo[c * KPAD + kc + 8]);
                #pragma unroll
                for (int i = 0; i < 4; i++) {
                    MMA_BF16(acc[i][j], ah[i], bh0, bh1);
                    MMA_BF16(acc[i][j], ah[i], bl0, bl1);
                    MMA_BF16(acc[i][j], al[i], bh0, bh1);
                }
            }
        }
        __syncthreads();
    }

    // epilogue: * norm_src, store fp32
    #pragma unroll
    for (int i = 0; i < 4; i++) {
        int r = warp_m * 64 + i * 16 + (lane >> 2);
        #pragma unroll
        for (int j = 0; j < 2; j++) {
            int c0 = warp_n * 16 + j * 8 + 2 * (lane & 3);
            #pragma unroll
            for (int hrow = 0; hrow < 2; hrow++) {
                int grow = m0 + r + 8 * hrow;
                if (grow >= n_nodes) continue;
                float ns = g_norm_src[grow];
                float2 v;
                v.x = acc[i][j][2 * hrow + 0] * ns;
                v.y = acc[i][j][2 * hrow + 1] * ns;
                *reinterpret_cast<float2*>(&g_ypre[(size_t)grow * OUT_DIM + c0]) = v;
            }
        }
    }
}

// ---------------- SpMM2: out[dst] += ypre[src], 8 edges/warp (half-warp per edge) ----------------
__global__ void k_spmm2(const int* __restrict__ src, const int* __restrict__ dst,
                        float* __restrict__ out, int n_edges) {
    int w = (blockIdx.x * blockDim.x + threadIdx.x) >> 5;
    int lane = threadIdx.x & 31;
    int half = lane >> 4;
    int l = lane & 15;
    int e0 = w * 8;
    if (e0 >= n_edges) return;
    int s[4], d[4];
    #pragma unroll
    for (int i = 0; i < 4; i++) {
        int e = min(e0 + 2 * i + half, n_edges - 1);
        s[i] = __ldg(&src[e]);
        d[i] = __ldg(&dst[e]);
    }
    float4 v[4];
    #pragma unroll
    for (int i = 0; i < 4; i++)
        v[i] = reinterpret_cast<const float4*>(g_ypre + (size_t)s[i] * OUT_DIM)[l];
    #pragma unroll
    for (int i = 0; i < 4; i++) {
        if (e0 + 2 * i + half >= n_edges) break;
        float4* orow = reinterpret_cast<float4*>(out + (size_t)d[i] * OUT_DIM);
        asm volatile("red.global.add.v4.f32 [%0], {%1,%2,%3,%4};"
                     :: "l"(orow + l), "f"(v[i].x), "f"(v[i].y), "f"(v[i].z), "f"(v[i].w)
                     : "memory");
    }
}

// ---------------- final: out = out * norm_dst[row] + b2[col] ----------------
__global__ void k_final(float* __restrict__ out, const float* __restrict__ b2, int n_nodes) {
    int i = blockIdx.x * blockDim.x + threadIdx.x;
    int total = n_nodes * (OUT_DIM / 4);
    if (i >= total) return;
    int row = i >> 4;
    int c4 = i & 15;
    float nd = g_norm_dst[row];
    float4 v = reinterpret_cast<float4*>(out)[i];
    const float4 bb = reinterpret_cast<const float4*>(b2)[c4];
    v.x = v.x * nd + bb.x;
    v.y = v.y * nd + bb.y;
    v.z = v.z * nd + bb.z;
    v.w = v.w * nd + bb.w;
    reinterpret_cast<float4*>(out)[i] = v;
}

// ---------------- launch ----------------
extern "C" void kernel_launch(void* const* d_in, const int* in_sizes, int n_in,
                              void* d_out, int out_size) {
    const float* h  = (const float*)d_in[0];
    const float* W1 = (const float*)d_in[1];
    const float* b1 = (const float*)d_in[2];
    const float* W2 = (const float*)d_in[3];
    const float* b2 = (const float*)d_in[4];
    const float* p  = (const float*)d_in[5];
    const int* src  = (const int*)d_in[6];
    const int* dst  = (const int*)d_in[7];

    const int n_nodes = in_sizes[0] / IN_DIM;   // 100000
    const int n_edges = in_sizes[6];            // 1600000
    float* out = (float*)d_out;

    k_zero<<<4096, 256>>>(reinterpret_cast<float4*>(out), n_nodes);
    k_degree<<<(n_edges + 255) / 256, 256>>>(src, dst, n_edges);
    k_norm<<<(n_nodes + 255) / 256, 256>>>(n_nodes);

    // SpMM1: 4 edges per warp
    {
        int warps = (n_edges + 3) / 4;
        k_spmm1<<<(warps + 7) / 8, 256>>>(h, src, dst, n_edges);
    }
    // GEMM1 (tensor core, bf16 split)
    {
        dim3 grid(NN_PAD / BM, HID_DIM / BN);   // 782 x 4
        k_gemm1<<<grid, 256>>>(W1, b1, p, n_nodes);
    }
    // GEMM2
    {
        dim3 grid(NN_PAD / BM, 1);              // 782
        k_gemm2<<<grid, 256>>>(W2, n_nodes);
    }
    // SpMM2: 8 edges per warp
    {
        int warps = (n_edges + 7) / 8;
        k_spmm2<<<(warps + 7) / 8, 256>>>(src, dst, out, n_edges);
    }
    k_final<<<(n_nodes * (OUT_DIM / 4) + 255) / 256, 256>>>(out, b2, n_nodes);
}